// round 7
// baseline (speedup 1.0000x reference)
#include <cuda_runtime.h>
#include <cuda_fp16.h>

#define N_NODES 100000
#define N_EDGES 1600000
#define D_IN    480
#define D_OUT   256
#define NEG_SLOPE 0.2f

// ---------------- scratch ----------------
__device__ float g_xl[(size_t)N_NODES * D_OUT];
__device__ float g_xr[(size_t)N_NODES * D_OUT];
__device__ int   g_counts[N_NODES];
__device__ int   g_offs[N_NODES];
__device__ int   g_wpos[N_NODES];
__device__ int   g_csrc[N_EDGES];
__device__ int   g_bsum[128];
__device__ int   g_bsum_ex[128];

// pack two fp32 -> one uint holding half2
__device__ __forceinline__ unsigned pack_half2(float lo, float hi) {
    unsigned r;
    asm("cvt.rn.f16x2.f32 %0, %1, %2;" : "=r"(r) : "f"(hi), "f"(lo));
    return r;
}

// ---------------- K0: init ----------------
__global__ void init_kernel() {
    int i = blockIdx.x * blockDim.x + threadIdx.x;
    if (i < N_NODES) g_counts[i] = 0;
}

// ---------------- K2: dst histogram ----------------
__global__ void hist_kernel(const int* __restrict__ ei) {
    int e = blockIdx.x * blockDim.x + threadIdx.x;
    if (e < N_EDGES) atomicAdd(&g_counts[ei[N_EDGES + e]], 1);
}

// ---------------- K1: pipelined dual GEMM, fp16 mma.m16n8k16, GBN=256 ----------------
// grid (2, 782): x=0 -> W_l -> g_xl ; x=1 -> W_r -> g_xr.  X read only twice total.
// Block 128(m) x 256(n), BK=32, 2-stage dynamic smem. 8 warps, each 64(m) x 64(n).
#define GBM 128
#define GBN2 256
#define GBK 32
#define SROW 20            // row stride in uint (half2) units = 40 halves; conflict-free frags
#define NIT (D_IN / GBK)   // 15
#define GEMM_SMEM ((2 * GBM * SROW + 2 * GBN2 * SROW) * 4)   // 61440 B

__global__ __launch_bounds__(256, 1)
void gemm_fp16_kernel(const float* __restrict__ X,
                      const float* __restrict__ W_l, const float* __restrict__ b_l,
                      const float* __restrict__ W_r, const float* __restrict__ b_r) {
    extern __shared__ unsigned smem_dyn[];
    unsigned* As = smem_dyn;                    // [2][GBM*SROW]
    unsigned* Bt = smem_dyn + 2 * GBM * SROW;   // [2][GBN2*SROW] transposed [n][k]

    int tx   = threadIdx.x;
    int lane = tx & 31;
    int wid  = tx >> 5;
    int warp_m = wid & 1;       // 0..1 (64-row tiles)
    int warp_n = wid >> 1;      // 0..3 (64-col tiles)
    int gid = lane >> 2;        // 0..7
    int tg  = lane & 3;         // 0..3

    int row0 = blockIdx.y * GBM;

    const float* W; const float* bv; float* Y;
    if (blockIdx.x == 0) { W = W_l; bv = b_l; Y = g_xl; }
    else                 { W = W_r; bv = b_r; Y = g_xr; }

    // A loader: 4 float4/thread: m = (tx>>3)+i*32, kq = tx&7
    int am  = tx >> 3;
    int akq = tx & 7;
    // B loader: 4 cells/thread: cell c = tx + i*256 -> kp = c&15, nq = c>>4 (0..63)
    int bkp = tx & 15;
    int bnq = tx >> 4;          // 0..15, +16 per i

    float4 ra[4];
    float4 rb[4][2];

    auto loadG = [&](int it) {
        int k0 = it * GBK;
#pragma unroll
        for (int i = 0; i < 4; i++) {
            int m  = am + i * 32;
            int gr = row0 + m;
            float4 v = make_float4(0.f, 0.f, 0.f, 0.f);
            if (gr < N_NODES)
                v = *reinterpret_cast<const float4*>(X + (size_t)gr * D_IN + k0 + akq * 4);
            ra[i] = v;
        }
#pragma unroll
        for (int i = 0; i < 4; i++) {
            int nq = bnq + i * 16;
            rb[i][0] = *reinterpret_cast<const float4*>(W + (size_t)(k0 + 2 * bkp) * D_OUT + nq * 4);
            rb[i][1] = *reinterpret_cast<const float4*>(W + (size_t)(k0 + 2 * bkp + 1) * D_OUT + nq * 4);
        }
    };
    auto storeS = [&](int buf) {
        unsigned* Ab = As + buf * (GBM * SROW);
        unsigned* Bb = Bt + buf * (GBN2 * SROW);
#pragma unroll
        for (int i = 0; i < 4; i++) {
            int m = am + i * 32;
            float4 v = ra[i];
            unsigned h01 = pack_half2(v.x, v.y);
            unsigned h23 = pack_half2(v.z, v.w);
            *reinterpret_cast<uint2*>(&Ab[m * SROW + akq * 2]) = make_uint2(h01, h23);
        }
#pragma unroll
        for (int i = 0; i < 4; i++) {
            int nq = bnq + i * 16;
            const float* lo = &rb[i][0].x;
            const float* hi = &rb[i][1].x;
#pragma unroll
            for (int j = 0; j < 4; j++) {
                Bb[(nq * 4 + j) * SROW + bkp] = pack_half2(lo[j], hi[j]);
            }
        }
    };

    float acc[4][8][4];
#pragma unroll
    for (int mt = 0; mt < 4; mt++)
#pragma unroll
        for (int nt = 0; nt < 8; nt++)
#pragma unroll
            for (int i = 0; i < 4; i++) acc[mt][nt][i] = 0.f;

    loadG(0);
    storeS(0);
    __syncthreads();

    for (int it = 0; it < NIT; it++) {
        unsigned* Ab = As + (it & 1) * (GBM * SROW);
        unsigned* Bb = Bt + (it & 1) * (GBN2 * SROW);
        if (it + 1 < NIT) loadG(it + 1);

#pragma unroll
        for (int ks = 0; ks < 2; ks++) {
            int ko = ks * 8;
            unsigned a[4][4];
#pragma unroll
            for (int mt = 0; mt < 4; mt++) {
                int r = warp_m * 64 + mt * 16 + gid;
                a[mt][0] = Ab[r * SROW + ko + tg];
                a[mt][1] = Ab[(r + 8) * SROW + ko + tg];
                a[mt][2] = Ab[r * SROW + ko + tg + 4];
                a[mt][3] = Ab[(r + 8) * SROW + ko + tg + 4];
            }
#pragma unroll
            for (int nt = 0; nt < 8; nt++) {
                int n = warp_n * 64 + nt * 8 + gid;
                unsigned b0 = Bb[n * SROW + ko + tg];
                unsigned b1 = Bb[n * SROW + ko + tg + 4];
#pragma unroll
                for (int mt = 0; mt < 4; mt++) {
                    asm volatile(
                        "mma.sync.aligned.m16n8k16.row.col.f32.f16.f16.f32 "
                        "{%0,%1,%2,%3}, {%4,%5,%6,%7}, {%8,%9}, {%0,%1,%2,%3};"
                        : "+f"(acc[mt][nt][0]), "+f"(acc[mt][nt][1]),
                          "+f"(acc[mt][nt][2]), "+f"(acc[mt][nt][3])
                        : "r"(a[mt][0]), "r"(a[mt][1]), "r"(a[mt][2]), "r"(a[mt][3]),
                          "r"(b0), "r"(b1));
                }
            }
        }

        if (it + 1 < NIT) storeS((it + 1) & 1);
        __syncthreads();
    }

#pragma unroll
    for (int mt = 0; mt < 4; mt++) {
        int r = row0 + warp_m * 64 + mt * 16 + gid;
#pragma unroll
        for (int nt = 0; nt < 8; nt++) {
            int c = warp_n * 64 + nt * 8 + tg * 2;
            if (r < N_NODES) {
                float2 v;
                v.x = acc[mt][nt][0] + bv[c];
                v.y = acc[mt][nt][1] + bv[c + 1];
                *reinterpret_cast<float2*>(Y + (size_t)r * D_OUT + c) = v;
            }
            if (r + 8 < N_NODES) {
                float2 v;
                v.x = acc[mt][nt][2] + bv[c];
                v.y = acc[mt][nt][3] + bv[c + 1];
                *reinterpret_cast<float2*>(Y + (size_t)(r + 8) * D_OUT + c) = v;
            }
        }
    }
}

// ---------------- K3: exclusive scan ----------------
#define SCAN_CH 1024
#define SCAN_NBLK ((N_NODES + SCAN_CH - 1) / SCAN_CH)   // 98

__global__ void scan1_kernel() {
    __shared__ int sh[SCAN_CH];
    int t = threadIdx.x;
    int g = blockIdx.x * SCAN_CH + t;
    int v = (g < N_NODES) ? g_counts[g] : 0;
    sh[t] = v;
    __syncthreads();
    for (int o = 1; o < SCAN_CH; o <<= 1) {
        int x = (t >= o) ? sh[t - o] : 0;
        __syncthreads();
        sh[t] += x;
        __syncthreads();
    }
    if (g < N_NODES) g_offs[g] = sh[t] - v;
    if (t == SCAN_CH - 1) g_bsum[blockIdx.x] = sh[t];
}

__global__ void scan2_kernel() {
    __shared__ int sh[128];
    int t = threadIdx.x;
    int v = (t < SCAN_NBLK) ? g_bsum[t] : 0;
    sh[t] = v;
    __syncthreads();
    for (int o = 1; o < 128; o <<= 1) {
        int x = (t >= o) ? sh[t - o] : 0;
        __syncthreads();
        sh[t] += x;
        __syncthreads();
    }
    if (t < SCAN_NBLK) g_bsum_ex[t] = sh[t] - v;
}

__global__ void scan3_kernel() {
    int g = blockIdx.x * SCAN_CH + threadIdx.x;
    if (g < N_NODES) {
        int v = g_offs[g] + g_bsum_ex[blockIdx.x];
        g_offs[g] = v;
        g_wpos[g] = v;
    }
}

// ---------------- K4: CSR scatter of src ids ----------------
__global__ void scatter_kernel(const int* __restrict__ ei) {
    int e = blockIdx.x * blockDim.x + threadIdx.x;
    if (e >= N_EDGES) return;
    int s = __ldg(&ei[e]);
    int d = __ldg(&ei[N_EDGES + e]);
    int pos = atomicAdd(&g_wpos[d], 1);
    g_csrc[pos] = s;
}

// ---------------- K5: fused logits+softmax+aggregate ----------------
__global__ __launch_bounds__(256)
void fused_node_kernel(const float* __restrict__ att,
                       const float* __restrict__ bias,
                       float* __restrict__ out) {
    int node = blockIdx.x * 8 + (threadIdx.x >> 5);
    if (node >= N_NODES) return;
    int lane = threadIdx.x & 31;
    int beg = g_offs[node];
    int cnt = g_counts[node];

    const float4* xrp = reinterpret_cast<const float4*>(g_xr + (size_t)node * D_OUT);
    const float4* atp = reinterpret_cast<const float4*>(att);
    float4 xr0 = xrp[lane], xr1 = xrp[lane + 32];
    float4 at0 = atp[lane], at1 = atp[lane + 32];

    float4 acc0 = make_float4(0.f, 0.f, 0.f, 0.f);
    float4 acc1 = make_float4(0.f, 0.f, 0.f, 0.f);
    float denom = 0.f;

    int s_reg = (lane < cnt) ? g_csrc[beg + lane] : 0;
    int batch = 0;

    int j = 0;
    for (; j + 2 <= cnt; j += 2) {
        if ((j >> 5) != batch) {
            batch = j >> 5;
            int idx = beg + batch * 32 + lane;
            s_reg = (batch * 32 + lane < cnt) ? g_csrc[idx] : 0;
        }
        int s0 = __shfl_sync(0xffffffffu, s_reg, j & 31);
        int s1;
        if (((j + 1) >> 5) != batch) {
            batch = (j + 1) >> 5;
            int idx = beg + batch * 32 + lane;
            s_reg = (batch * 32 + lane < cnt) ? g_csrc[idx] : 0;
            s1 = __shfl_sync(0xffffffffu, s_reg, (j + 1) & 31);
        } else {
            s1 = __shfl_sync(0xffffffffu, s_reg, (j + 1) & 31);
        }

        const float4* xp0 = reinterpret_cast<const float4*>(g_xl + (size_t)s0 * D_OUT);
        const float4* xp1 = reinterpret_cast<const float4*>(g_xl + (size_t)s1 * D_OUT);
        float4 a0 = xp0[lane], b0 = xp0[lane + 32];
        float4 a1 = xp1[lane], b1 = xp1[lane + 32];

        float p0 = 0.f, p1 = 0.f, h;
        h = a0.x + xr0.x; h = h > 0.f ? h : NEG_SLOPE * h; p0 = fmaf(at0.x, h, p0);
        h = a0.y + xr0.y; h = h > 0.f ? h : NEG_SLOPE * h; p0 = fmaf(at0.y, h, p0);
        h = a0.z + xr0.z; h = h > 0.f ? h : NEG_SLOPE * h; p0 = fmaf(at0.z, h, p0);
        h = a0.w + xr0.w; h = h > 0.f ? h : NEG_SLOPE * h; p0 = fmaf(at0.w, h, p0);
        h = b0.x + xr1.x; h = h > 0.f ? h : NEG_SLOPE * h; p0 = fmaf(at1.x, h, p0);
        h = b0.y + xr1.y; h = h > 0.f ? h : NEG_SLOPE * h; p0 = fmaf(at1.y, h, p0);
        h = b0.z + xr1.z; h = h > 0.f ? h : NEG_SLOPE * h; p0 = fmaf(at1.z, h, p0);
        h = b0.w + xr1.w; h = h > 0.f ? h : NEG_SLOPE * h; p0 = fmaf(at1.w, h, p0);
        h = a1.x + xr0.x; h = h > 0.f ? h : NEG_SLOPE * h; p1 = fmaf(at0.x, h, p1);
        h = a1.y + xr0.y; h = h > 0.f ? h : NEG_SLOPE * h; p1 = fmaf(at0.y, h, p1);
        h = a1.z + xr0.z; h = h > 0.f ? h : NEG_SLOPE * h; p1 = fmaf(at0.z, h, p1);
        h = a1.w + xr0.w; h = h > 0.f ? h : NEG_SLOPE * h; p1 = fmaf(at0.w, h, p1);
        h = b1.x + xr1.x; h = h > 0.f ? h : NEG_SLOPE * h; p1 = fmaf(at1.x, h, p1);
        h = b1.y + xr1.y; h = h > 0.f ? h : NEG_SLOPE * h; p1 = fmaf(at1.y, h, p1);
        h = b1.z + xr1.z; h = h > 0.f ? h : NEG_SLOPE * h; p1 = fmaf(at1.z, h, p1);
        h = b1.w + xr1.w; h = h > 0.f ? h : NEG_SLOPE * h; p1 = fmaf(at1.w, h, p1);

#pragma unroll
        for (int o = 16; o > 0; o >>= 1) {
            p0 += __shfl_xor_sync(0xffffffffu, p0, o);
            p1 += __shfl_xor_sync(0xffffffffu, p1, o);
        }
        float w0 = __expf(p0);
        float w1 = __expf(p1);
        denom += w0 + w1;
        acc0.x = fmaf(w0, a0.x, acc0.x); acc0.y = fmaf(w0, a0.y, acc0.y);
        acc0.z = fmaf(w0, a0.z, acc0.z); acc0.w = fmaf(w0, a0.w, acc0.w);
        acc1.x = fmaf(w0, b0.x, acc1.x); acc1.y = fmaf(w0, b0.y, acc1.y);
        acc1.z = fmaf(w0, b0.z, acc1.z); acc1.w = fmaf(w0, b0.w, acc1.w);
        acc0.x = fmaf(w1, a1.x, acc0.x); acc0.y = fmaf(w1, a1.y, acc0.y);
        acc0.z = fmaf(w1, a1.z, acc0.z); acc0.w = fmaf(w1, a1.w, acc0.w);
        acc1.x = fmaf(w1, b1.x, acc1.x); acc1.y = fmaf(w1, b1.y, acc1.y);
        acc1.z = fmaf(w1, b1.z, acc1.z); acc1.w = fmaf(w1, b1.w, acc1.w);
    }
    if (j < cnt) {
        if ((j >> 5) != batch) {
            batch = j >> 5;
            int idx = beg + batch * 32 + lane;
            s_reg = (batch * 32 + lane < cnt) ? g_csrc[idx] : 0;
        }
        int s0 = __shfl_sync(0xffffffffu, s_reg, j & 31);
        const float4* xp0 = reinterpret_cast<const float4*>(g_xl + (size_t)s0 * D_OUT);
        float4 a0 = xp0[lane], b0 = xp0[lane + 32];
        float p0 = 0.f, h;
        h = a0.x + xr0.x; h = h > 0.f ? h : NEG_SLOPE * h; p0 = fmaf(at0.x, h, p0);
        h = a0.y + xr0.y; h = h > 0.f ? h : NEG_SLOPE * h; p0 = fmaf(at0.y, h, p0);
        h = a0.z + xr0.z; h = h > 0.f ? h : NEG_SLOPE * h; p0 = fmaf(at0.z, h, p0);
        h = a0.w + xr0.w; h = h > 0.f ? h : NEG_SLOPE * h; p0 = fmaf(at0.w, h, p0);
        h = b0.x + xr1.x; h = h > 0.f ? h : NEG_SLOPE * h; p0 = fmaf(at1.x, h, p0);
        h = b0.y + xr1.y; h = h > 0.f ? h : NEG_SLOPE * h; p0 = fmaf(at1.y, h, p0);
        h = b0.z + xr1.z; h = h > 0.f ? h : NEG_SLOPE * h; p0 = fmaf(at1.z, h, p0);
        h = b0.w + xr1.w; h = h > 0.f ? h : NEG_SLOPE * h; p0 = fmaf(at1.w, h, p0);
#pragma unroll
        for (int o = 16; o > 0; o >>= 1) p0 += __shfl_xor_sync(0xffffffffu, p0, o);
        float w0 = __expf(p0);
        denom += w0;
        acc0.x = fmaf(w0, a0.x, acc0.x); acc0.y = fmaf(w0, a0.y, acc0.y);
        acc0.z = fmaf(w0, a0.z, acc0.z); acc0.w = fmaf(w0, a0.w, acc0.w);
        acc1.x = fmaf(w0, b0.x, acc1.x); acc1.y = fmaf(w0, b0.y, acc1.y);
        acc1.z = fmaf(w0, b0.z, acc1.z); acc1.w = fmaf(w0, b0.w, acc1.w);
    }

    float rd = 1.f / (denom + 1e-16f);
    const float4* bi = reinterpret_cast<const float4*>(bias);
    float4 bb0 = bi[lane], bb1 = bi[lane + 32];
    float4 o0 = make_float4(fmaf(acc0.x, rd, bb0.x), fmaf(acc0.y, rd, bb0.y),
                            fmaf(acc0.z, rd, bb0.z), fmaf(acc0.w, rd, bb0.w));
    float4 o1 = make_float4(fmaf(acc1.x, rd, bb1.x), fmaf(acc1.y, rd, bb1.y),
                            fmaf(acc1.z, rd, bb1.z), fmaf(acc1.w, rd, bb1.w));
    float4* op = reinterpret_cast<float4*>(out + (size_t)node * D_OUT);
    op[lane]      = o0;
    op[lane + 32] = o1;
}

// ---------------- launch ----------------
extern "C" void kernel_launch(void* const* d_in, const int* in_sizes, int n_in,
                              void* d_out, int out_size) {
    const float* x    = (const float*)d_in[0];
    const int*   ei   = (const int*)d_in[1];
    const float* W_l  = (const float*)d_in[2];
    const float* b_l  = (const float*)d_in[3];
    const float* W_r  = (const float*)d_in[4];
    const float* b_r  = (const float*)d_in[5];
    const float* att  = (const float*)d_in[6];
    const float* bias = (const float*)d_in[7];
    float* out = (float*)d_out;

    cudaFuncSetAttribute(gemm_fp16_kernel,
                         cudaFuncAttributeMaxDynamicSharedMemorySize, GEMM_SMEM);

    init_kernel<<<(N_NODES + 255) / 256, 256>>>();
    hist_kernel<<<(N_EDGES + 255) / 256, 256>>>(ei);

    dim3 ggrid(2, (N_NODES + GBM - 1) / GBM);   // (2, 782)
    gemm_fp16_kernel<<<ggrid, 256, GEMM_SMEM>>>(x, W_l, b_l, W_r, b_r);

    scan1_kernel<<<SCAN_NBLK, SCAN_CH>>>();
    scan2_kernel<<<1, 128>>>();
    scan3_kernel<<<SCAN_NBLK, SCAN_CH>>>();

    scatter_kernel<<<(N_EDGES + 255) / 256, 256>>>(ei);

    fused_node_kernel<<<(N_NODES + 7) / 8, 256>>>(att, bias, out);
}

// round 8
// speedup vs baseline: 1.1102x; 1.1102x over previous
#include <cuda_runtime.h>
#include <cuda_fp16.h>

#define N_NODES 100000
#define N_EDGES 1600000
#define D_IN    480
#define D_OUT   256
#define NEG_SLOPE 0.2f

// ---------------- scratch ----------------
// node features stored as half2-packed uints: row = 128 uints = 256 halves
__device__ unsigned g_xl_h[(size_t)N_NODES * (D_OUT / 2)];
__device__ unsigned g_xr_h[(size_t)N_NODES * (D_OUT / 2)];
__device__ int      g_counts[N_NODES];
__device__ int      g_offs[N_NODES];
__device__ int      g_wpos[N_NODES];
__device__ int      g_csrc[N_EDGES];
__device__ int      g_bsum[128];
__device__ int      g_bsum_ex[128];

__device__ __forceinline__ float tf32r(float x) {
    unsigned r;
    asm("cvt.rna.tf32.f32 %0, %1;" : "=r"(r) : "f"(x));
    return __uint_as_float(r);
}
__device__ __forceinline__ unsigned pack_half2(float lo, float hi) {
    unsigned r;
    asm("cvt.rn.f16x2.f32 %0, %1, %2;" : "=r"(r) : "f"(hi), "f"(lo));
    return r;
}
__device__ __forceinline__ float2 h2f2(unsigned u) {
    __half2 h = *reinterpret_cast<__half2*>(&u);
    return __half22float2(h);
}

// ---------------- K0: init ----------------
__global__ void init_kernel() {
    int i = blockIdx.x * blockDim.x + threadIdx.x;
    if (i < N_NODES) g_counts[i] = 0;
}

// ---------------- K2: dst histogram ----------------
__global__ void hist_kernel(const int* __restrict__ ei) {
    int e = blockIdx.x * blockDim.x + threadIdx.x;
    if (e < N_EDGES) atomicAdd(&g_counts[ei[N_EDGES + e]], 1);
}

// ---------------- K1: pipelined dual GEMM via tf32 mma.sync (round-4 config) ----------------
// epilogue writes fp16 (half2-packed) node features.
#define GBM 128
#define GBN 128
#define GBK 16
#define PADA 20
#define PADB 136
#define NIT (D_IN / GBK)   // 30

__global__ __launch_bounds__(256, 2)
void gemm_tf32_kernel(const float* __restrict__ X,
                      const float* __restrict__ W_l, const float* __restrict__ b_l,
                      const float* __restrict__ W_r, const float* __restrict__ b_r) {
    __shared__ float As[2][GBM * PADA];
    __shared__ float Bs[2][GBK * PADB];

    int tx   = threadIdx.x;
    int lane = tx & 31;
    int wid  = tx >> 5;
    int warp_m = wid & 3;
    int warp_n = wid >> 2;

    int row0 = blockIdx.y * GBM;
    int col0 = blockIdx.x * GBN;

    const float* W; const float* bv; unsigned* Yh;
    int wc = col0;
    if (col0 < D_OUT) { W = W_l; bv = b_l; Yh = g_xl_h; }
    else              { W = W_r; bv = b_r; Yh = g_xr_h; wc = col0 - D_OUT; }

    int am  = (tx >> 2);
    int akq = (tx & 3);
    int bk  = (tx >> 5);
    int bnq = (tx & 31);

    float4 ra[2], rb[2];

    auto loadG = [&](int it) {
#pragma unroll
        for (int i = 0; i < 2; i++) {
            int m  = am + i * 64;
            int gr = row0 + m;
            float4 v = make_float4(0.f, 0.f, 0.f, 0.f);
            if (gr < N_NODES)
                v = *reinterpret_cast<const float4*>(X + (size_t)gr * D_IN + it * GBK + akq * 4);
            ra[i] = v;
        }
#pragma unroll
        for (int i = 0; i < 2; i++) {
            int k = bk + i * 8;
            rb[i] = *reinterpret_cast<const float4*>(W + (size_t)(it * GBK + k) * D_OUT + wc + bnq * 4);
        }
    };
    auto storeS = [&](int buf) {
#pragma unroll
        for (int i = 0; i < 2; i++) {
            int m = am + i * 64;
            float4 v = ra[i];
            v.x = tf32r(v.x); v.y = tf32r(v.y); v.z = tf32r(v.z); v.w = tf32r(v.w);
            *reinterpret_cast<float4*>(&As[buf][m * PADA + akq * 4]) = v;
        }
#pragma unroll
        for (int i = 0; i < 2; i++) {
            int k = bk + i * 8;
            float4 v = rb[i];
            v.x = tf32r(v.x); v.y = tf32r(v.y); v.z = tf32r(v.z); v.w = tf32r(v.w);
            *reinterpret_cast<float4*>(&Bs[buf][k * PADB + bnq * 4]) = v;
        }
    };

    float acc[2][8][4];
#pragma unroll
    for (int mt = 0; mt < 2; mt++)
#pragma unroll
        for (int nt = 0; nt < 8; nt++)
#pragma unroll
            for (int i = 0; i < 4; i++) acc[mt][nt][i] = 0.f;

    loadG(0);
    storeS(0);
    __syncthreads();

    for (int it = 0; it < NIT; it++) {
        int cur = it & 1;
        if (it + 1 < NIT) loadG(it + 1);

#pragma unroll
        for (int ks = 0; ks < 2; ks++) {
            int kk = ks * 8 + (lane & 3);
            unsigned a[2][4];
#pragma unroll
            for (int mt = 0; mt < 2; mt++) {
                int r = warp_m * 32 + mt * 16 + (lane >> 2);
                a[mt][0] = __float_as_uint(As[cur][r * PADA + kk]);
                a[mt][1] = __float_as_uint(As[cur][(r + 8) * PADA + kk]);
                a[mt][2] = __float_as_uint(As[cur][r * PADA + kk + 4]);
                a[mt][3] = __float_as_uint(As[cur][(r + 8) * PADA + kk + 4]);
            }
#pragma unroll
            for (int nt = 0; nt < 8; nt++) {
                int n = warp_n * 64 + nt * 8 + (lane >> 2);
                unsigned b0 = __float_as_uint(Bs[cur][kk * PADB + n]);
                unsigned b1 = __float_as_uint(Bs[cur][(kk + 4) * PADB + n]);
#pragma unroll
                for (int mt = 0; mt < 2; mt++) {
                    asm volatile(
                        "mma.sync.aligned.m16n8k8.row.col.f32.tf32.tf32.f32 "
                        "{%0,%1,%2,%3}, {%4,%5,%6,%7}, {%8,%9}, {%0,%1,%2,%3};"
                        : "+f"(acc[mt][nt][0]), "+f"(acc[mt][nt][1]),
                          "+f"(acc[mt][nt][2]), "+f"(acc[mt][nt][3])
                        : "r"(a[mt][0]), "r"(a[mt][1]), "r"(a[mt][2]), "r"(a[mt][3]),
                          "r"(b0), "r"(b1));
                }
            }
        }

        if (it + 1 < NIT) storeS((it + 1) & 1);
        __syncthreads();
    }

#pragma unroll
    for (int mt = 0; mt < 2; mt++) {
        int r = row0 + warp_m * 32 + mt * 16 + (lane >> 2);
#pragma unroll
        for (int nt = 0; nt < 8; nt++) {
            int c = wc + warp_n * 64 + nt * 8 + (lane & 3) * 2;
            if (r < N_NODES) {
                Yh[(size_t)r * (D_OUT / 2) + (c >> 1)] =
                    pack_half2(acc[mt][nt][0] + bv[c], acc[mt][nt][1] + bv[c + 1]);
            }
            if (r + 8 < N_NODES) {
                Yh[(size_t)(r + 8) * (D_OUT / 2) + (c >> 1)] =
                    pack_half2(acc[mt][nt][2] + bv[c], acc[mt][nt][3] + bv[c + 1]);
            }
        }
    }
}

// ---------------- K3: exclusive scan ----------------
#define SCAN_CH 1024
#define SCAN_NBLK ((N_NODES + SCAN_CH - 1) / SCAN_CH)   // 98

__global__ void scan1_kernel() {
    __shared__ int sh[SCAN_CH];
    int t = threadIdx.x;
    int g = blockIdx.x * SCAN_CH + t;
    int v = (g < N_NODES) ? g_counts[g] : 0;
    sh[t] = v;
    __syncthreads();
    for (int o = 1; o < SCAN_CH; o <<= 1) {
        int x = (t >= o) ? sh[t - o] : 0;
        __syncthreads();
        sh[t] += x;
        __syncthreads();
    }
    if (g < N_NODES) g_offs[g] = sh[t] - v;
    if (t == SCAN_CH - 1) g_bsum[blockIdx.x] = sh[t];
}

__global__ void scan2_kernel() {
    __shared__ int sh[128];
    int t = threadIdx.x;
    int v = (t < SCAN_NBLK) ? g_bsum[t] : 0;
    sh[t] = v;
    __syncthreads();
    for (int o = 1; o < 128; o <<= 1) {
        int x = (t >= o) ? sh[t - o] : 0;
        __syncthreads();
        sh[t] += x;
        __syncthreads();
    }
    if (t < SCAN_NBLK) g_bsum_ex[t] = sh[t] - v;
}

__global__ void scan3_kernel() {
    int g = blockIdx.x * SCAN_CH + threadIdx.x;
    if (g < N_NODES) {
        int v = g_offs[g] + g_bsum_ex[blockIdx.x];
        g_offs[g] = v;
        g_wpos[g] = v;
    }
}

// ---------------- K4: CSR scatter of src ids ----------------
__global__ void scatter_kernel(const int* __restrict__ ei) {
    int e = blockIdx.x * blockDim.x + threadIdx.x;
    if (e >= N_EDGES) return;
    int s = __ldg(&ei[e]);
    int d = __ldg(&ei[N_EDGES + e]);
    int pos = atomicAdd(&g_wpos[d], 1);
    g_csrc[pos] = s;
}

// ---------------- K5: fused logits+softmax+aggregate (fp16 features) ----------------
// one warp per node; each lane owns channels [lane*8, lane*8+8)
__global__ __launch_bounds__(256)
void fused_node_kernel(const float* __restrict__ att,
                       const float* __restrict__ bias,
                       float* __restrict__ out) {
    int node = blockIdx.x * 8 + (threadIdx.x >> 5);
    if (node >= N_NODES) return;
    int lane = threadIdx.x & 31;
    int beg = g_offs[node];
    int cnt = g_counts[node];

    // xr slice: one uint4 = 8 halves
    uint4 xru = *reinterpret_cast<const uint4*>(g_xr_h + (size_t)node * 128 + lane * 4);
    float xr[8];
    { float2 f;
      f = h2f2(xru.x); xr[0] = f.x; xr[1] = f.y;
      f = h2f2(xru.y); xr[2] = f.x; xr[3] = f.y;
      f = h2f2(xru.z); xr[4] = f.x; xr[5] = f.y;
      f = h2f2(xru.w); xr[6] = f.x; xr[7] = f.y; }
    float at[8];
    { const float4* atp = reinterpret_cast<const float4*>(att);
      float4 a0 = atp[lane * 2], a1 = atp[lane * 2 + 1];
      at[0] = a0.x; at[1] = a0.y; at[2] = a0.z; at[3] = a0.w;
      at[4] = a1.x; at[5] = a1.y; at[6] = a1.z; at[7] = a1.w; }

    float acc[8];
#pragma unroll
    for (int i = 0; i < 8; i++) acc[i] = 0.f;
    float denom = 0.f;

    int s_reg = (lane < cnt) ? g_csrc[beg + lane] : 0;
    int batch = 0;

    int j = 0;
    for (; j + 2 <= cnt; j += 2) {
        if ((j >> 5) != batch) {
            batch = j >> 5;
            int idx = beg + batch * 32 + lane;
            s_reg = (batch * 32 + lane < cnt) ? g_csrc[idx] : 0;
        }
        int s0 = __shfl_sync(0xffffffffu, s_reg, j & 31);
        int s1;
        if (((j + 1) >> 5) != batch) {
            batch = (j + 1) >> 5;
            int idx = beg + batch * 32 + lane;
            s_reg = (batch * 32 + lane < cnt) ? g_csrc[idx] : 0;
            s1 = __shfl_sync(0xffffffffu, s_reg, (j + 1) & 31);
        } else {
            s1 = __shfl_sync(0xffffffffu, s_reg, (j + 1) & 31);
        }

        uint4 u0 = *reinterpret_cast<const uint4*>(g_xl_h + (size_t)s0 * 128 + lane * 4);
        uint4 u1 = *reinterpret_cast<const uint4*>(g_xl_h + (size_t)s1 * 128 + lane * 4);

        float x0[8], x1[8];
        { float2 f;
          f = h2f2(u0.x); x0[0] = f.x; x0[1] = f.y;
          f = h2f2(u0.y); x0[2] = f.x; x0[3] = f.y;
          f = h2f2(u0.z); x0[4] = f.x; x0[5] = f.y;
          f = h2f2(u0.w); x0[6] = f.x; x0[7] = f.y;
          f = h2f2(u1.x); x1[0] = f.x; x1[1] = f.y;
          f = h2f2(u1.y); x1[2] = f.x; x1[3] = f.y;
          f = h2f2(u1.z); x1[4] = f.x; x1[5] = f.y;
          f = h2f2(u1.w); x1[6] = f.x; x1[7] = f.y; }

        float p0 = 0.f, p1 = 0.f;
#pragma unroll
        for (int i = 0; i < 8; i++) {
            float h0 = x0[i] + xr[i]; h0 = h0 > 0.f ? h0 : NEG_SLOPE * h0;
            float h1 = x1[i] + xr[i]; h1 = h1 > 0.f ? h1 : NEG_SLOPE * h1;
            p0 = fmaf(at[i], h0, p0);
            p1 = fmaf(at[i], h1, p1);
        }
#pragma unroll
        for (int o = 16; o > 0; o >>= 1) {
            p0 += __shfl_xor_sync(0xffffffffu, p0, o);
            p1 += __shfl_xor_sync(0xffffffffu, p1, o);
        }
        float w0 = __expf(p0);
        float w1 = __expf(p1);
        denom += w0 + w1;
#pragma unroll
        for (int i = 0; i < 8; i++) {
            acc[i] = fmaf(w0, x0[i], acc[i]);
            acc[i] = fmaf(w1, x1[i], acc[i]);
        }
    }
    if (j < cnt) {
        if ((j >> 5) != batch) {
            batch = j >> 5;
            int idx = beg + batch * 32 + lane;
            s_reg = (batch * 32 + lane < cnt) ? g_csrc[idx] : 0;
        }
        int s0 = __shfl_sync(0xffffffffu, s_reg, j & 31);
        uint4 u0 = *reinterpret_cast<const uint4*>(g_xl_h + (size_t)s0 * 128 + lane * 4);
        float x0[8];
        { float2 f;
          f = h2f2(u0.x); x0[0] = f.x; x0[1] = f.y;
          f = h2f2(u0.y); x0[2] = f.x; x0[3] = f.y;
          f = h2f2(u0.z); x0[4] = f.x; x0[5] = f.y;
          f = h2f2(u0.w); x0[6] = f.x; x0[7] = f.y; }
        float p0 = 0.f;
#pragma unroll
        for (int i = 0; i < 8; i++) {
            float h0 = x0[i] + xr[i]; h0 = h0 > 0.f ? h0 : NEG_SLOPE * h0;
            p0 = fmaf(at[i], h0, p0);
        }
#pragma unroll
        for (int o = 16; o > 0; o >>= 1) p0 += __shfl_xor_sync(0xffffffffu, p0, o);
        float w0 = __expf(p0);
        denom += w0;
#pragma unroll
        for (int i = 0; i < 8; i++) acc[i] = fmaf(w0, x0[i], acc[i]);
    }

    float rd = 1.f / (denom + 1e-16f);
    const float4* bi = reinterpret_cast<const float4*>(bias);
    float4 bb0 = bi[lane * 2], bb1 = bi[lane * 2 + 1];
    float4 o0 = make_float4(fmaf(acc[0], rd, bb0.x), fmaf(acc[1], rd, bb0.y),
                            fmaf(acc[2], rd, bb0.z), fmaf(acc[3], rd, bb0.w));
    float4 o1 = make_float4(fmaf(acc[4], rd, bb1.x), fmaf(acc[5], rd, bb1.y),
                            fmaf(acc[6], rd, bb1.z), fmaf(acc[7], rd, bb1.w));
    float4* op = reinterpret_cast<float4*>(out + (size_t)node * D_OUT + lane * 8);
    op[0] = o0;
    op[1] = o1;
}

// ---------------- launch ----------------
extern "C" void kernel_launch(void* const* d_in, const int* in_sizes, int n_in,
                              void* d_out, int out_size) {
    const float* x    = (const float*)d_in[0];
    const int*   ei   = (const int*)d_in[1];
    const float* W_l  = (const float*)d_in[2];
    const float* b_l  = (const float*)d_in[3];
    const float* W_r  = (const float*)d_in[4];
    const float* b_r  = (const float*)d_in[5];
    const float* att  = (const float*)d_in[6];
    const float* bias = (const float*)d_in[7];
    float* out = (float*)d_out;

    init_kernel<<<(N_NODES + 255) / 256, 256>>>();
    hist_kernel<<<(N_EDGES + 255) / 256, 256>>>(ei);

    dim3 ggrid(2 * D_OUT / GBN, (N_NODES + GBM - 1) / GBM);   // (4, 782)
    gemm_tf32_kernel<<<ggrid, 256>>>(x, W_l, b_l, W_r, b_r);

    scan1_kernel<<<SCAN_NBLK, SCAN_CH>>>();
    scan2_kernel<<<1, 128>>>();
    scan3_kernel<<<SCAN_NBLK, SCAN_CH>>>();

    scatter_kernel<<<(N_EDGES + 255) / 256, 256>>>(ei);

    fused_node_kernel<<<(N_NODES + 7) / 8, 256>>>(att, bias, out);
}